// round 3
// baseline (speedup 1.0000x reference)
#include <cuda_runtime.h>
#include <cuda_bf16.h>
#include <cstdint>

// ---------------- problem constants ----------------
#define NROWS 8000      // B*(T-K) rows of p
#define NCOLS 8176      // B*(T-1)  rows of zn

// ---------------- static scratch ----------------
__device__ float g_h1[8192 * 512];
__device__ float g_h2[8192 * 512];
__device__ float g_xi[8192 * 1536];
__device__ float g_ph[8000 * 512];
__device__ float g_p [8000 * 256];
__device__ float g_zn[8176 * 256];
__device__ float g_hbuf[2][8192];       // GRU hidden, layout [col*16 + row]
__device__ float g_E[8000];
__device__ float g_low [8000 * 11];
__device__ float g_high[8000 * 11];
__device__ float g_diag[8000 * 12];
__device__ unsigned g_bar;

// ---------------- reset ----------------
__global__ void reset_kernel() {
    int idx = blockIdx.x * blockDim.x + threadIdx.x;
    int stride = gridDim.x * blockDim.x;
    for (int i = idx; i < 8000; i += stride) g_E[i] = 0.f;
    for (int i = idx; i < 8000 * 11; i += stride) { g_low[i] = 0.f; g_high[i] = 0.f; }
    for (int i = idx; i < 2 * 8192; i += stride) ((float*)g_hbuf)[i] = 0.f;
    if (idx == 0) g_bar = 0u;
}

// ---------------- SGEMM: C[M,N] = act(A[M,K] @ W[K,N] + bias) ----------------
// 128x128 tile, BK=8, 256 threads, 8x8 per thread. N%128==0, K%8==0 guaranteed.
// rowmap==1: logical row r reads physical row r + (r/500)*12   (c[:, :-12] view)
__global__ __launch_bounds__(256) void sgemm128(
    const float* __restrict__ A, const float* __restrict__ W,
    const float* __restrict__ bias, float* __restrict__ C,
    int M, int N, int K, int doRelu, int rowmap)
{
    __shared__ float As[8][128];
    __shared__ float Bs[8][132];
    int tid = threadIdx.x;
    int bx = blockIdx.x, by = blockIdx.y;
    int tx = tid & 15, ty = tid >> 4;

    int arow = tid >> 1;
    int acol = (tid & 1) << 2;
    int grow = by * 128 + arow;
    bool aval = grow < M;
    long ar = grow;
    if (rowmap && aval) ar = grow + (grow / 500) * 12;
    const float* Ap = A + (size_t)ar * K + acol;

    int brow = tid >> 5;
    int bcol = (tid & 31) << 2;
    const float* Bp = W + (size_t)brow * N + (size_t)bx * 128 + bcol;

    float acc[8][8];
#pragma unroll
    for (int i = 0; i < 8; i++)
#pragma unroll
        for (int j = 0; j < 8; j++) acc[i][j] = 0.f;

    for (int k0 = 0; k0 < K; k0 += 8) {
        float4 av = aval ? *(const float4*)(Ap + k0) : make_float4(0.f,0.f,0.f,0.f);
        float4 bv = *(const float4*)(Bp + (size_t)k0 * N);
        As[acol + 0][arow] = av.x; As[acol + 1][arow] = av.y;
        As[acol + 2][arow] = av.z; As[acol + 3][arow] = av.w;
        *(float4*)&Bs[brow][bcol] = bv;
        __syncthreads();
#pragma unroll
        for (int kk = 0; kk < 8; kk++) {
            float a[8], b[8];
            *(float4*)&a[0] = *(const float4*)&As[kk][ty * 8];
            *(float4*)&a[4] = *(const float4*)&As[kk][ty * 8 + 4];
            *(float4*)&b[0] = *(const float4*)&Bs[kk][tx * 8];
            *(float4*)&b[4] = *(const float4*)&Bs[kk][tx * 8 + 4];
#pragma unroll
            for (int i = 0; i < 8; i++)
#pragma unroll
                for (int j = 0; j < 8; j++) acc[i][j] = fmaf(a[i], b[j], acc[i][j]);
        }
        __syncthreads();
    }

    int cbase = bx * 128 + tx * 8;
#pragma unroll
    for (int i = 0; i < 8; i++) {
        int r = by * 128 + ty * 8 + i;
        if (r >= M) continue;
        float* Cp = C + (size_t)r * N + cbase;
#pragma unroll
        for (int j = 0; j < 8; j++) {
            float v = acc[i][j] + bias[cbase + j];
            if (doRelu) v = fmaxf(v, 0.f);
            Cp[j] = v;
        }
    }
}

// ---------------- GRU persistent kernel ----------------
// 128 CTAs x 256 threads, all co-resident (128 < 148 SMs). CTA owns 4 cols x 3
// gates; its 24KB weight slice lives in smem for all 512 steps. h ping-pongs in
// global (read via ldcg). Grid barrier = atomic counter.
__global__ __launch_bounds__(256) void gru_kernel(
    const float* __restrict__ wh, const float* __restrict__ bhn,
    float* __restrict__ cOut)
{
    __shared__ float w_s[12 * 512];
    __shared__ float red[192 * 17];
    __shared__ float dot_s[192];
    __shared__ float bhn_s[4];
    int tid = threadIdx.x;
    int colBase = blockIdx.x * 4;

    for (int e = tid; e < 6144; e += 256) {
        int gc = e >> 9, k = e & 511;
        int g = gc >> 2, cc = gc & 3;
        w_s[e] = wh[(size_t)k * 1536 + g * 512 + colBase + cc];
    }
    if (tid < 4) bhn_s[tid] = bhn[colBase + tid];
    __syncthreads();

    int ks = tid >> 4;        // 0..15 k-split
    int row = tid & 15;       // batch
    int grow2 = tid >> 2;     // gate thread: batch row (tid<64)
    int gcol = colBase + (tid & 3);

    for (int t = 0; t < 512; t++) {
        int rb = t & 1;
        const float* hb = g_hbuf[rb];

        float xr = 0.f, xu = 0.f, xn = 0.f, hold = 0.f;
        if (tid < 64) {
            size_t base = ((size_t)(grow2 << 9) + t) * 1536 + gcol;
            xr = __ldg(&g_xi[base]);
            xu = __ldg(&g_xi[base + 512]);
            xn = __ldg(&g_xi[base + 1024]);
            hold = __ldcg(&hb[gcol * 16 + grow2]);
        }

        float acc[12];
#pragma unroll
        for (int g = 0; g < 12; g++) acc[g] = 0.f;
#pragma unroll 8
        for (int kk = 0; kk < 32; kk++) {
            int k = ks + (kk << 4);
            float hv = __ldcg(&hb[k * 16 + row]);
#pragma unroll
            for (int g = 0; g < 12; g++) acc[g] = fmaf(w_s[g * 512 + k], hv, acc[g]);
        }
#pragma unroll
        for (int g = 0; g < 12; g++) red[(row * 12 + g) * 17 + ks] = acc[g];
        __syncthreads();

        if (tid < 192) {
            float v = 0.f;
#pragma unroll
            for (int s = 0; s < 16; s++) v += red[tid * 17 + s];
            dot_s[tid] = v;
        }
        __syncthreads();

        if (tid < 64) {
            int cc = tid & 3;
            float hr = dot_s[grow2 * 12 + cc];
            float hu = dot_s[grow2 * 12 + 4 + cc];
            float hn = dot_s[grow2 * 12 + 8 + cc];
            float r = 1.f / (1.f + __expf(-(xr + hr)));
            float u = 1.f / (1.f + __expf(-(xu + hu)));
            float n = tanhf(xn + r * (hn + bhn_s[cc]));
            float hnew = (1.f - u) * n + u * hold;
            g_hbuf[rb ^ 1][gcol * 16 + grow2] = hnew;
            cOut[((size_t)(grow2 << 9) + t) * 512 + gcol] = hnew;
        }

        __threadfence();
        __syncthreads();
        if (tid == 0) {
            atomicAdd(&g_bar, 1u);
            unsigned tgt = (unsigned)gridDim.x * (unsigned)(t + 1);
            while (*((volatile unsigned*)&g_bar) < tgt) { }
            __threadfence();
        }
        __syncthreads();
    }
}

// ---------------- row L2-normalize (256-wide rows), one warp per row ----------------
__device__ __forceinline__ void norm_row(const float* src, float* dst, int lane, float extraScale) {
    float4 a = ((const float4*)src)[lane];
    float4 b = ((const float4*)src)[lane + 32];
    float ss = a.x*a.x + a.y*a.y + a.z*a.z + a.w*a.w
             + b.x*b.x + b.y*b.y + b.z*b.z + b.w*b.w;
#pragma unroll
    for (int o = 16; o > 0; o >>= 1) ss += __shfl_xor_sync(0xffffffffu, ss, o);
    float r = rsqrtf(ss);
    r = r * (1.5f - 0.5f * ss * r * r);   // Newton refine
    r *= extraScale;
    a.x*=r; a.y*=r; a.z*=r; a.w*=r; b.x*=r; b.y*=r; b.z*=r; b.w*=r;
    ((float4*)dst)[lane] = a;
    ((float4*)dst)[lane + 32] = b;
}

__global__ void norm_p_kernel() {
    int w = (blockIdx.x * blockDim.x + threadIdx.x) >> 5;
    if (w >= NROWS) return;
    // fold 1/TEMP into p so the Gram product is sim directly
    norm_row(g_p + (size_t)w * 256, g_p + (size_t)w * 256, threadIdx.x & 31, 10.0f);
}

__global__ void build_zn_kernel(const float* __restrict__ z) {
    int w = (blockIdx.x * blockDim.x + threadIdx.x) >> 5;
    if (w >= NCOLS) return;
    int b = w / 511, tt = w % 511;
    const float* src = z + (size_t)(b * 512 + tt + 1) * 256;
    norm_row(src, g_zn + (size_t)w * 256, threadIdx.x & 31, 1.0f);
}

// ---------------- fused Gram + shifted-exp epilogue ----------------
// s = (p/|p|)·(z/|z|)/TEMP, |s|<=10. e = exp(s-10); accumulate per-row E,
// 11 low / 11 high boundary column sums, and the 12 diagonal raw s values.
__global__ __launch_bounds__(256) void gram_kernel() {
    __shared__ float As[8][128];
    __shared__ float Bs[8][132];
    __shared__ float red[128][17];
    int tid = threadIdx.x;
    int bx = blockIdx.x, by = blockIdx.y;
    int tx = tid & 15, ty = tid >> 4;

    int arow = tid >> 1;
    int acol = (tid & 1) << 2;
    int ga = by * 128 + arow; bool av = ga < NROWS;
    int gb = bx * 128 + arow; bool bvv = gb < NCOLS;
    const float* Ap = g_p  + (size_t)ga * 256 + acol;
    const float* Bp = g_zn + (size_t)gb * 256 + acol;

    float acc[8][8];
#pragma unroll
    for (int i = 0; i < 8; i++)
#pragma unroll
        for (int j = 0; j < 8; j++) acc[i][j] = 0.f;

    for (int k0 = 0; k0 < 256; k0 += 8) {
        float4 a4 = av  ? *(const float4*)(Ap + k0) : make_float4(0.f,0.f,0.f,0.f);
        float4 b4 = bvv ? *(const float4*)(Bp + k0) : make_float4(0.f,0.f,0.f,0.f);
        As[acol + 0][arow] = a4.x; As[acol + 1][arow] = a4.y;
        As[acol + 2][arow] = a4.z; As[acol + 3][arow] = a4.w;
        Bs[acol + 0][arow] = b4.x; Bs[acol + 1][arow] = b4.y;
        Bs[acol + 2][arow] = b4.z; Bs[acol + 3][arow] = b4.w;
        __syncthreads();
#pragma unroll
        for (int kk = 0; kk < 8; kk++) {
            float a[8], b[8];
            *(float4*)&a[0] = *(const float4*)&As[kk][ty * 8];
            *(float4*)&a[4] = *(const float4*)&As[kk][ty * 8 + 4];
            *(float4*)&b[0] = *(const float4*)&Bs[kk][tx * 8];
            *(float4*)&b[4] = *(const float4*)&Bs[kk][tx * 8 + 4];
#pragma unroll
            for (int i = 0; i < 8; i++)
#pragma unroll
                for (int j = 0; j < 8; j++) acc[i][j] = fmaf(a[i], b[j], acc[i][j]);
        }
        __syncthreads();
    }

    int mg[8], mmv[8], mbv[8];
#pragma unroll
    for (int j = 0; j < 8; j++) {
        mg[j]  = bx * 128 + tx * 8 + j;
        mmv[j] = mg[j] % 511;
        mbv[j] = mg[j] / 511;
    }
#pragma unroll
    for (int i = 0; i < 8; i++) {
        int ig = by * 128 + ty * 8 + i;
        float rsum = 0.f;
        if (ig < NROWS) {
            int bi = ig / 500, ti = ig % 500;
#pragma unroll
            for (int j = 0; j < 8; j++) {
                if (mg[j] < NCOLS) {
                    float s = acc[i][j];
                    float e = __expf(s - 10.0f);
                    rsum += e;
                    int mm = mmv[j];
                    if (mm < 11) atomicAdd(&g_low[ig * 11 + mm], e);
                    else if (mm >= 500) atomicAdd(&g_high[ig * 11 + mm - 500], e);
                    if (mbv[j] == bi) {
                        int dd = mm - ti;
                        if (dd >= 0 && dd < 12) g_diag[ig * 12 + dd] = s;
                    }
                }
            }
        }
        red[ty * 8 + i][tx] = rsum;
    }
    __syncthreads();
    if (tid < 128) {
        int rr = by * 128 + tid;
        if (rr < NROWS) {
            float v = 0.f;
#pragma unroll
            for (int s2 = 0; s2 < 16; s2++) v += red[tid][s2];
            atomicAdd(&g_E[rr], v);
        }
    }
}

// ---------------- loss finisher ----------------
__global__ void loss_kernel(float* __restrict__ out) {
    __shared__ float part[1024];
    int tid = threadIdx.x;
    float tot = 0.f;
    for (int i = tid; i < NROWS; i += 1024) {
        float E = g_E[i];
        float L[11], H[11];
        float low = 0.f, high = 0.f;
#pragma unroll
        for (int j = 0; j < 11; j++) {
            L[j] = g_low[i * 11 + j];
            H[j] = g_high[i * 11 + j];
            high += H[j];
        }
#pragma unroll
        for (int k = 1; k <= 12; k++) {
            if (k >= 2) { low += L[k - 2]; high -= H[k - 2]; }
            float window = E - low - high;
            tot += g_diag[i * 12 + (k - 1)] - (10.0f + logf(window));
        }
    }
    part[tid] = tot;
    __syncthreads();
    for (int s = 512; s > 0; s >>= 1) {
        if (tid < s) part[tid] += part[tid + s];
        __syncthreads();
    }
    if (tid == 0) out[0] = -part[0] / (12.0f * (float)NROWS);
}

// ---------------- driver ----------------
extern "C" void kernel_launch(void* const* d_in, const int* in_sizes, int n_in,
                              void* d_out, int out_size) {
    const float* x       = (const float*)d_in[0];
    const float* enc_w1  = (const float*)d_in[1];
    const float* enc_b1  = (const float*)d_in[2];
    const float* enc_w2  = (const float*)d_in[3];
    const float* enc_b2  = (const float*)d_in[4];
    const float* enc_w3  = (const float*)d_in[5];
    const float* enc_b3  = (const float*)d_in[6];
    const float* gru_wi  = (const float*)d_in[7];
    const float* gru_bi  = (const float*)d_in[8];
    const float* gru_wh  = (const float*)d_in[9];
    const float* gru_bhn = (const float*)d_in[10];
    const float* pred_w1 = (const float*)d_in[11];
    const float* pred_b1 = (const float*)d_in[12];
    const float* pred_w2 = (const float*)d_in[13];
    const float* pred_b2 = (const float*)d_in[14];

    float* out  = (float*)d_out;
    float* zOut = out;                       // [8192, 256]
    float* cOut = out + 2097152;             // [8192, 512]
    float* lOut = out + (out_size - 1);

    // CRITICAL: resolve real device addresses of the scratch symbols.
    // (Taking &g_xi in host code yields the HOST shadow symbol — on GB300
    // with ATS the GPU can dereference it, silently writing host memory.)
    float *h1, *h2, *xi, *ph, *p;
    cudaGetSymbolAddress((void**)&h1, g_h1);
    cudaGetSymbolAddress((void**)&h2, g_h2);
    cudaGetSymbolAddress((void**)&xi, g_xi);
    cudaGetSymbolAddress((void**)&ph, g_ph);
    cudaGetSymbolAddress((void**)&p,  g_p);

    reset_kernel<<<64, 256>>>();

    dim3 t256(256);
    // encoder
    sgemm128<<<dim3(4, 64),  t256>>>(x,    enc_w1, enc_b1, h1,   8192, 512,  128, 1, 0);
    sgemm128<<<dim3(4, 64),  t256>>>(h1,   enc_w2, enc_b2, h2,   8192, 512,  512, 1, 0);
    sgemm128<<<dim3(2, 64),  t256>>>(h2,   enc_w3, enc_b3, zOut, 8192, 256,  512, 0, 0);
    // GRU input projection
    sgemm128<<<dim3(12, 64), t256>>>(zOut, gru_wi, gru_bi, xi,   8192, 1536, 256, 0, 0);
    // GRU recurrence
    gru_kernel<<<128, 256>>>(gru_wh, gru_bhn, cOut);
    // prediction net on c[:, :-12]
    sgemm128<<<dim3(4, 63),  t256>>>(cOut, pred_w1, pred_b1, ph, 8000, 512,  512, 1, 1);
    sgemm128<<<dim3(2, 63),  t256>>>(ph,   pred_w2, pred_b2, p,  8000, 256,  512, 0, 0);
    // normalize
    norm_p_kernel<<<1000, 256>>>();
    build_zn_kernel<<<1022, 256>>>(zOut);
    // fused Gram + epilogue
    gram_kernel<<<dim3(64, 63), t256>>>();
    // loss
    loss_kernel<<<1, 1024>>>(lOut);
}

// round 4
// speedup vs baseline: 1.1734x; 1.1734x over previous
#include <cuda_runtime.h>
#include <cuda_bf16.h>
#include <cstdint>

// ---------------- problem constants ----------------
#define NROWS 8000      // B*(T-K) rows of p
#define NCOLS 8176      // B*(T-1)  rows of zn

// ---------------- static scratch ----------------
__device__ float g_h1[8192 * 512];
__device__ float g_h2[8192 * 512];
__device__ float g_xi[8192 * 1536];
__device__ float g_ph[8000 * 512];
__device__ float g_p [8000 * 256];
__device__ float g_zn[8176 * 256];
__device__ float g_hbuf[2][8192];
__device__ float g_E[8000];
__device__ float g_low [8000 * 11];
__device__ float g_high[8000 * 11];
__device__ float g_diag[8000 * 12];
__device__ unsigned g_bar;

// ---------------- reset ----------------
__global__ void reset_kernel() {
    int idx = blockIdx.x * blockDim.x + threadIdx.x;
    int stride = gridDim.x * blockDim.x;
    for (int i = idx; i < 8000; i += stride) g_E[i] = 0.f;
    for (int i = idx; i < 8000 * 11; i += stride) { g_low[i] = 0.f; g_high[i] = 0.f; }
    for (int i = idx; i < 2 * 8192; i += stride) ((float*)g_hbuf)[i] = 0.f;
    if (idx == 0) g_bar = 0u;
}

// ---------------- fp32 SIMT SGEMM (kept for enc chain + xi: bit-accuracy of z,c) ----
__global__ __launch_bounds__(256) void sgemm128(
    const float* __restrict__ A, const float* __restrict__ W,
    const float* __restrict__ bias, float* __restrict__ C,
    int M, int N, int K, int doRelu, int rowmap)
{
    __shared__ float As[8][128];
    __shared__ float Bs[8][132];
    int tid = threadIdx.x;
    int bx = blockIdx.x, by = blockIdx.y;
    int tx = tid & 15, ty = tid >> 4;

    int arow = tid >> 1;
    int acol = (tid & 1) << 2;
    int grow = by * 128 + arow;
    bool aval = grow < M;
    long ar = grow;
    if (rowmap && aval) ar = grow + (grow / 500) * 12;
    const float* Ap = A + (size_t)ar * K + acol;

    int brow = tid >> 5;
    int bcol = (tid & 31) << 2;
    const float* Bp = W + (size_t)brow * N + (size_t)bx * 128 + bcol;

    float acc[8][8];
#pragma unroll
    for (int i = 0; i < 8; i++)
#pragma unroll
        for (int j = 0; j < 8; j++) acc[i][j] = 0.f;

    for (int k0 = 0; k0 < K; k0 += 8) {
        float4 av = aval ? *(const float4*)(Ap + k0) : make_float4(0.f,0.f,0.f,0.f);
        float4 bv = *(const float4*)(Bp + (size_t)k0 * N);
        As[acol + 0][arow] = av.x; As[acol + 1][arow] = av.y;
        As[acol + 2][arow] = av.z; As[acol + 3][arow] = av.w;
        *(float4*)&Bs[brow][bcol] = bv;
        __syncthreads();
#pragma unroll
        for (int kk = 0; kk < 8; kk++) {
            float a[8], b[8];
            *(float4*)&a[0] = *(const float4*)&As[kk][ty * 8];
            *(float4*)&a[4] = *(const float4*)&As[kk][ty * 8 + 4];
            *(float4*)&b[0] = *(const float4*)&Bs[kk][tx * 8];
            *(float4*)&b[4] = *(const float4*)&Bs[kk][tx * 8 + 4];
#pragma unroll
            for (int i = 0; i < 8; i++)
#pragma unroll
                for (int j = 0; j < 8; j++) acc[i][j] = fmaf(a[i], b[j], acc[i][j]);
        }
        __syncthreads();
    }

    int cbase = bx * 128 + tx * 8;
#pragma unroll
    for (int i = 0; i < 8; i++) {
        int r = by * 128 + ty * 8 + i;
        if (r >= M) continue;
        float* Cp = C + (size_t)r * N + cbase;
#pragma unroll
        for (int j = 0; j < 8; j++) {
            float v = acc[i][j] + bias[cbase + j];
            if (doRelu) v = fmaxf(v, 0.f);
            Cp[j] = v;
        }
    }
}

// ---------------- tf32 helpers ----------------
__device__ __forceinline__ uint32_t f2tf32(float v) {
    uint32_t r;
    asm("cvt.rna.tf32.f32 %0, %1;" : "=r"(r) : "f"(v));
    return r;
}
__device__ __forceinline__ void mma_tf32(
    float& c0, float& c1, float& c2, float& c3,
    uint32_t a0, uint32_t a1, uint32_t a2, uint32_t a3,
    uint32_t b0, uint32_t b1)
{
    asm volatile(
        "mma.sync.aligned.m16n8k8.row.col.f32.tf32.tf32.f32 "
        "{%0,%1,%2,%3}, {%4,%5,%6,%7}, {%8,%9}, {%0,%1,%2,%3};"
        : "+f"(c0), "+f"(c1), "+f"(c2), "+f"(c3)
        : "r"(a0), "r"(a1), "r"(a2), "r"(a3), "r"(b0), "r"(b1));
}

// ---------------- tf32 tensor GEMM ----------------
// C[M,N] = act(A[M,K] @ B + bias). CTA tile 128x128, BK=32, 8 warps (4m x 2n),
// warp tile 32x64 via m16n8k8.
// BMODE 0: B is weights [K][N] row-major (transpose-load into Bs[n][k])
// BMODE 1: B is [N][K] row-major (gram: zn; direct load)
// EPI 0: write C with bias/relu.  EPI 1: gram epilogue (exp/E/boundary/diag).
#define SA 36
#define SB 37
template<int BMODE, int EPI>
__global__ __launch_bounds__(256) void tmma_kernel(
    const float* __restrict__ A, const float* __restrict__ B,
    const float* __restrict__ bias, float* __restrict__ C,
    int M, int N, int K, int doRelu, int rowmap)
{
    __shared__ uint32_t As[128 * SA];
    __shared__ uint32_t Bs[128 * SB];
    __shared__ float red[128];

    int tid = threadIdx.x;
    int bx = blockIdx.x, by = blockIdx.y;
    int wid = tid >> 5, lane = tid & 31;
    int wm = wid >> 1, wn = wid & 1;        // warp grid 4(m) x 2(n)
    int g = lane >> 2, tg = lane & 3;

    if (EPI == 1 && tid < 128) red[tid] = 0.f;

    // A load indexing: 2 threads per row, 16 k each
    int arow = tid >> 1;
    int akh = (tid & 1) << 4;
    int agrow = by * 128 + arow;
    bool aval = agrow < M;
    long ar = agrow;
    if (rowmap && aval) ar = agrow + (agrow / 500) * 12;
    const float* Ap = A + (size_t)ar * K + akh;

    // B load indexing
    int bn_d = tid >> 1;                    // BMODE 1: row n
    int bkh_d = (tid & 1) << 4;
    int bgn_d = bx * 128 + bn_d;
    const float* Bp_d = B + (size_t)bgn_d * K + bkh_d;   // [N][K]
    int bn_t = tid & 127;                   // BMODE 0: col n
    int bkh_t = (tid >> 7) << 4;
    const float* Bp_t = B + (size_t)(bx * 128 + bn_t);   // [K][N]

    float acc[2][8][4];
#pragma unroll
    for (int mi = 0; mi < 2; mi++)
#pragma unroll
        for (int ni = 0; ni < 8; ni++)
#pragma unroll
            for (int q = 0; q < 4; q++) acc[mi][ni][q] = 0.f;

    for (int k0 = 0; k0 < K; k0 += 32) {
        // stage A
#pragma unroll
        for (int i = 0; i < 4; i++) {
            float4 v = aval ? *(const float4*)(Ap + k0 + i * 4)
                            : make_float4(0.f,0.f,0.f,0.f);
            uint32_t* d = &As[arow * SA + akh + i * 4];
            d[0] = f2tf32(v.x); d[1] = f2tf32(v.y);
            d[2] = f2tf32(v.z); d[3] = f2tf32(v.w);
        }
        // stage B
        if (BMODE == 1) {
            bool bv = bgn_d < N;
#pragma unroll
            for (int i = 0; i < 4; i++) {
                float4 v = bv ? *(const float4*)(Bp_d + k0 + i * 4)
                              : make_float4(0.f,0.f,0.f,0.f);
                uint32_t* d = &Bs[bn_d * SB + bkh_d + i * 4];
                d[0] = f2tf32(v.x); d[1] = f2tf32(v.y);
                d[2] = f2tf32(v.z); d[3] = f2tf32(v.w);
            }
        } else {
#pragma unroll
            for (int j = 0; j < 16; j++) {
                int k = bkh_t + j;
                float v = Bp_t[(size_t)(k0 + k) * N];
                Bs[bn_t * SB + k] = f2tf32(v);
            }
        }
        __syncthreads();

#pragma unroll
        for (int ks = 0; ks < 4; ks++) {
            int kb = ks * 8;
            uint32_t a[2][4];
#pragma unroll
            for (int mi = 0; mi < 2; mi++) {
                int r = wm * 32 + mi * 16;
                a[mi][0] = As[(r + g    ) * SA + kb + tg];
                a[mi][1] = As[(r + g + 8) * SA + kb + tg];
                a[mi][2] = As[(r + g    ) * SA + kb + tg + 4];
                a[mi][3] = As[(r + g + 8) * SA + kb + tg + 4];
            }
#pragma unroll
            for (int ni = 0; ni < 8; ni++) {
                int n = wn * 64 + ni * 8;
                uint32_t b0 = Bs[(n + g) * SB + kb + tg];
                uint32_t b1 = Bs[(n + g) * SB + kb + tg + 4];
#pragma unroll
                for (int mi = 0; mi < 2; mi++)
                    mma_tf32(acc[mi][ni][0], acc[mi][ni][1],
                             acc[mi][ni][2], acc[mi][ni][3],
                             a[mi][0], a[mi][1], a[mi][2], a[mi][3], b0, b1);
            }
        }
        __syncthreads();
    }

    if (EPI == 0) {
        // bias + optional relu, write C
#pragma unroll
        for (int mi = 0; mi < 2; mi++) {
            int r0 = by * 128 + wm * 32 + mi * 16 + g;
#pragma unroll
            for (int ni = 0; ni < 8; ni++) {
                int cg = bx * 128 + wn * 64 + ni * 8 + tg * 2;
                float b0v = bias[cg], b1v = bias[cg + 1];
                float v0 = acc[mi][ni][0] + b0v;
                float v1 = acc[mi][ni][1] + b1v;
                float v2 = acc[mi][ni][2] + b0v;
                float v3 = acc[mi][ni][3] + b1v;
                if (doRelu) {
                    v0 = fmaxf(v0, 0.f); v1 = fmaxf(v1, 0.f);
                    v2 = fmaxf(v2, 0.f); v3 = fmaxf(v3, 0.f);
                }
                if (r0 < M)     *(float2*)&C[(size_t)r0 * N + cg]       = make_float2(v0, v1);
                if (r0 + 8 < M) *(float2*)&C[(size_t)(r0 + 8) * N + cg] = make_float2(v2, v3);
            }
        }
    } else {
        // gram epilogue: s in acc (p pre-scaled by 1/TEMP). e = exp(s-10).
        float rsum[2][2] = {{0.f,0.f},{0.f,0.f}};
#pragma unroll
        for (int ni = 0; ni < 8; ni++) {
            int cg0 = bx * 128 + wn * 64 + ni * 8 + tg * 2;
#pragma unroll
            for (int half = 0; half < 2; half++) {  // column cg0+half
                int cg = cg0 + half;
                if (cg >= NCOLS) continue;
                int cb = cg / 511;
                int mm = cg - cb * 511;
#pragma unroll
                for (int mi = 0; mi < 2; mi++) {
#pragma unroll
                    for (int rh = 0; rh < 2; rh++) {
                        int rg = by * 128 + wm * 32 + mi * 16 + rh * 8 + g;
                        if (rg >= NROWS) continue;
                        float s = acc[mi][ni][rh * 2 + half];
                        float e = __expf(s - 10.0f);
                        rsum[mi][rh] += e;
                        if (mm < 11) atomicAdd(&g_low[rg * 11 + mm], e);
                        else if (mm >= 500) atomicAdd(&g_high[rg * 11 + mm - 500], e);
                        int bi = rg / 500;
                        if (cb == bi) {
                            int dd = mm - (rg - bi * 500);
                            if (dd >= 0 && dd < 12) g_diag[rg * 12 + dd] = s;
                        }
                    }
                }
            }
        }
        // reduce row sums across the 4 lanes sharing g (tg = 0..3)
#pragma unroll
        for (int mi = 0; mi < 2; mi++)
#pragma unroll
            for (int rh = 0; rh < 2; rh++) {
                float v = rsum[mi][rh];
                v += __shfl_xor_sync(0xffffffffu, v, 1);
                v += __shfl_xor_sync(0xffffffffu, v, 2);
                if (tg == 0)
                    atomicAdd(&red[wm * 32 + mi * 16 + rh * 8 + g], v);
            }
        __syncthreads();
        if (tid < 128) {
            int rr = by * 128 + tid;
            if (rr < NROWS && red[tid] != 0.f) atomicAdd(&g_E[rr], red[tid]);
        }
    }
}

// ---------------- GRU persistent kernel (unchanged, works) ----------------
__global__ __launch_bounds__(256) void gru_kernel(
    const float* __restrict__ wh, const float* __restrict__ bhn,
    float* __restrict__ cOut)
{
    __shared__ float w_s[12 * 512];
    __shared__ float red[192 * 17];
    __shared__ float dot_s[192];
    __shared__ float bhn_s[4];
    int tid = threadIdx.x;
    int colBase = blockIdx.x * 4;

    for (int e = tid; e < 6144; e += 256) {
        int gc = e >> 9, k = e & 511;
        int g = gc >> 2, cc = gc & 3;
        w_s[e] = wh[(size_t)k * 1536 + g * 512 + colBase + cc];
    }
    if (tid < 4) bhn_s[tid] = bhn[colBase + tid];
    __syncthreads();

    int ks = tid >> 4;
    int row = tid & 15;
    int grow2 = tid >> 2;
    int gcol = colBase + (tid & 3);

    for (int t = 0; t < 512; t++) {
        int rb = t & 1;
        const float* hb = g_hbuf[rb];

        float xr = 0.f, xu = 0.f, xn = 0.f, hold = 0.f;
        if (tid < 64) {
            size_t base = ((size_t)(grow2 << 9) + t) * 1536 + gcol;
            xr = __ldg(&g_xi[base]);
            xu = __ldg(&g_xi[base + 512]);
            xn = __ldg(&g_xi[base + 1024]);
            hold = __ldcg(&hb[gcol * 16 + grow2]);
        }

        float acc[12];
#pragma unroll
        for (int g = 0; g < 12; g++) acc[g] = 0.f;
#pragma unroll 8
        for (int kk = 0; kk < 32; kk++) {
            int k = ks + (kk << 4);
            float hv = __ldcg(&hb[k * 16 + row]);
#pragma unroll
            for (int g = 0; g < 12; g++) acc[g] = fmaf(w_s[g * 512 + k], hv, acc[g]);
        }
#pragma unroll
        for (int g = 0; g < 12; g++) red[(row * 12 + g) * 17 + ks] = acc[g];
        __syncthreads();

        if (tid < 192) {
            float v = 0.f;
#pragma unroll
            for (int s = 0; s < 16; s++) v += red[tid * 17 + s];
            dot_s[tid] = v;
        }
        __syncthreads();

        if (tid < 64) {
            int cc = tid & 3;
            float hr = dot_s[grow2 * 12 + cc];
            float hu = dot_s[grow2 * 12 + 4 + cc];
            float hn = dot_s[grow2 * 12 + 8 + cc];
            float r = 1.f / (1.f + __expf(-(xr + hr)));
            float u = 1.f / (1.f + __expf(-(xu + hu)));
            float n = tanhf(xn + r * (hn + bhn_s[cc]));
            float hnew = (1.f - u) * n + u * hold;
            g_hbuf[rb ^ 1][gcol * 16 + grow2] = hnew;
            cOut[((size_t)(grow2 << 9) + t) * 512 + gcol] = hnew;
        }

        __threadfence();
        __syncthreads();
        if (tid == 0) {
            atomicAdd(&g_bar, 1u);
            unsigned tgt = (unsigned)gridDim.x * (unsigned)(t + 1);
            while (*((volatile unsigned*)&g_bar) < tgt) { }
            __threadfence();
        }
        __syncthreads();
    }
}

// ---------------- row L2-normalize ----------------
__device__ __forceinline__ void norm_row(const float* src, float* dst, int lane, float extraScale) {
    float4 a = ((const float4*)src)[lane];
    float4 b = ((const float4*)src)[lane + 32];
    float ss = a.x*a.x + a.y*a.y + a.z*a.z + a.w*a.w
             + b.x*b.x + b.y*b.y + b.z*b.z + b.w*b.w;
#pragma unroll
    for (int o = 16; o > 0; o >>= 1) ss += __shfl_xor_sync(0xffffffffu, ss, o);
    float r = rsqrtf(ss);
    r = r * (1.5f - 0.5f * ss * r * r);
    r *= extraScale;
    a.x*=r; a.y*=r; a.z*=r; a.w*=r; b.x*=r; b.y*=r; b.z*=r; b.w*=r;
    ((float4*)dst)[lane] = a;
    ((float4*)dst)[lane + 32] = b;
}

__global__ void norm_p_kernel() {
    int w = (blockIdx.x * blockDim.x + threadIdx.x) >> 5;
    if (w >= NROWS) return;
    norm_row(g_p + (size_t)w * 256, g_p + (size_t)w * 256, threadIdx.x & 31, 10.0f);
}

__global__ void build_zn_kernel(const float* __restrict__ z) {
    int w = (blockIdx.x * blockDim.x + threadIdx.x) >> 5;
    if (w >= NCOLS) return;
    int b = w / 511, tt = w % 511;
    const float* src = z + (size_t)(b * 512 + tt + 1) * 256;
    norm_row(src, g_zn + (size_t)w * 256, threadIdx.x & 31, 1.0f);
}

// ---------------- loss finisher ----------------
__global__ void loss_kernel(float* __restrict__ out) {
    __shared__ float part[1024];
    int tid = threadIdx.x;
    float tot = 0.f;
    for (int i = tid; i < NROWS; i += 1024) {
        float E = g_E[i];
        float L[11], H[11];
        float low = 0.f, high = 0.f;
#pragma unroll
        for (int j = 0; j < 11; j++) {
            L[j] = g_low[i * 11 + j];
            H[j] = g_high[i * 11 + j];
            high += H[j];
        }
#pragma unroll
        for (int k = 1; k <= 12; k++) {
            if (k >= 2) { low += L[k - 2]; high -= H[k - 2]; }
            float window = E - low - high;
            tot += g_diag[i * 12 + (k - 1)] - (10.0f + logf(window));
        }
    }
    part[tid] = tot;
    __syncthreads();
    for (int s = 512; s > 0; s >>= 1) {
        if (tid < s) part[tid] += part[tid + s];
        __syncthreads();
    }
    if (tid == 0) out[0] = -part[0] / (12.0f * (float)NROWS);
}

// ---------------- driver ----------------
extern "C" void kernel_launch(void* const* d_in, const int* in_sizes, int n_in,
                              void* d_out, int out_size) {
    const float* x       = (const float*)d_in[0];
    const float* enc_w1  = (const float*)d_in[1];
    const float* enc_b1  = (const float*)d_in[2];
    const float* enc_w2  = (const float*)d_in[3];
    const float* enc_b2  = (const float*)d_in[4];
    const float* enc_w3  = (const float*)d_in[5];
    const float* enc_b3  = (const float*)d_in[6];
    const float* gru_wi  = (const float*)d_in[7];
    const float* gru_bi  = (const float*)d_in[8];
    const float* gru_wh  = (const float*)d_in[9];
    const float* gru_bhn = (const float*)d_in[10];
    const float* pred_w1 = (const float*)d_in[11];
    const float* pred_b1 = (const float*)d_in[12];
    const float* pred_w2 = (const float*)d_in[13];
    const float* pred_b2 = (const float*)d_in[14];

    float* out  = (float*)d_out;
    float* zOut = out;                       // [8192, 256]
    float* cOut = out + 2097152;             // [8192, 512]
    float* lOut = out + (out_size - 1);

    // Resolve true device addresses of scratch symbols (host-shadow trap!)
    float *h1, *h2, *xi, *ph, *p, *zn;
    cudaGetSymbolAddress((void**)&h1, g_h1);
    cudaGetSymbolAddress((void**)&h2, g_h2);
    cudaGetSymbolAddress((void**)&xi, g_xi);
    cudaGetSymbolAddress((void**)&ph, g_ph);
    cudaGetSymbolAddress((void**)&p,  g_p);
    cudaGetSymbolAddress((void**)&zn, g_zn);

    reset_kernel<<<64, 256>>>();

    dim3 t256(256);
    // encoder (fp32 — z exactness)
    sgemm128<<<dim3(4, 64),  t256>>>(x,    enc_w1, enc_b1, h1,   8192, 512,  128, 1, 0);
    sgemm128<<<dim3(4, 64),  t256>>>(h1,   enc_w2, enc_b2, h2,   8192, 512,  512, 1, 0);
    sgemm128<<<dim3(2, 64),  t256>>>(h2,   enc_w3, enc_b3, zOut, 8192, 256,  512, 0, 0);
    // GRU input projection (fp32 — c accuracy)
    sgemm128<<<dim3(12, 64), t256>>>(zOut, gru_wi, gru_bi, xi,   8192, 1536, 256, 0, 0);
    // GRU recurrence
    gru_kernel<<<128, 256>>>(gru_wh, gru_bhn, cOut);
    // prediction net on c[:, :-12] — tf32 tensor cores (loss-only path)
    tmma_kernel<0,0><<<dim3(4, 63), t256>>>(cOut, pred_w1, pred_b1, ph, 8000, 512, 512, 1, 1);
    tmma_kernel<0,0><<<dim3(2, 63), t256>>>(ph,   pred_w2, pred_b2, p,  8000, 256, 512, 0, 0);
    // normalize
    norm_p_kernel<<<1000, 256>>>();
    build_zn_kernel<<<1022, 256>>>(zOut);
    // fused Gram + epilogue — tf32 tensor cores
    tmma_kernel<1,1><<<dim3(64, 63), t256>>>(p, zn, nullptr, nullptr, NROWS, NCOLS, 256, 0, 0);
    // loss
    loss_kernel<<<1, 1024>>>(lOut);
}

// round 5
// speedup vs baseline: 1.3224x; 1.1270x over previous
#include <cuda_runtime.h>
#include <cuda_bf16.h>
#include <cstdint>

// ---------------- problem constants ----------------
#define NROWS 8000      // B*(T-K) rows of p
#define NCOLS 8176      // B*(T-1)  rows of zn

// ---------------- static scratch ----------------
__device__ float g_h1[8192 * 512];
__device__ float g_h2[8192 * 512];
__device__ float g_xi[8192 * 1536];
__device__ float g_ph[8000 * 512];
__device__ float g_p [8000 * 256];
__device__ float g_zn[8176 * 256];
__device__ float g_hbuf[2][8192];
__device__ float g_E[8000];
__device__ float g_low [8000 * 11];
__device__ float g_high[8000 * 11];
__device__ float g_diag[8000 * 12];
__device__ unsigned g_bar;

// ---------------- scoped sync helpers (no L1-flushing fences) ----------------
__device__ __forceinline__ unsigned ld_acquire_gpu(const unsigned* p) {
    unsigned v;
    asm volatile("ld.acquire.gpu.u32 %0, [%1];" : "=r"(v) : "l"(p) : "memory");
    return v;
}
__device__ __forceinline__ void red_release_gpu(unsigned* p, unsigned v) {
    asm volatile("red.release.gpu.add.u32 [%0], %1;" :: "l"(p), "r"(v) : "memory");
}
__device__ __forceinline__ void stcg(float* p, float v) {
    asm volatile("st.global.cg.f32 [%0], %1;" :: "l"(p), "f"(v) : "memory");
}

// ---------------- reset ----------------
__global__ void reset_kernel() {
    int idx = blockIdx.x * blockDim.x + threadIdx.x;
    int stride = gridDim.x * blockDim.x;
    for (int i = idx; i < 8000; i += stride) g_E[i] = 0.f;
    for (int i = idx; i < 8000 * 11; i += stride) { g_low[i] = 0.f; g_high[i] = 0.f; }
    for (int i = idx; i < 2 * 8192; i += stride) ((float*)g_hbuf)[i] = 0.f;
    if (idx == 0) g_bar = 0u;
}

// ---------------- fp32 SIMT SGEMM (enc chain + xi: bit-accuracy of z,c) ----------
__global__ __launch_bounds__(256) void sgemm128(
    const float* __restrict__ A, const float* __restrict__ W,
    const float* __restrict__ bias, float* __restrict__ C,
    int M, int N, int K, int doRelu, int rowmap)
{
    __shared__ float As[8][128];
    __shared__ float Bs[8][132];
    int tid = threadIdx.x;
    int bx = blockIdx.x, by = blockIdx.y;
    int tx = tid & 15, ty = tid >> 4;

    int arow = tid >> 1;
    int acol = (tid & 1) << 2;
    int grow = by * 128 + arow;
    bool aval = grow < M;
    long ar = grow;
    if (rowmap && aval) ar = grow + (grow / 500) * 12;
    const float* Ap = A + (size_t)ar * K + acol;

    int brow = tid >> 5;
    int bcol = (tid & 31) << 2;
    const float* Bp = W + (size_t)brow * N + (size_t)bx * 128 + bcol;

    float acc[8][8];
#pragma unroll
    for (int i = 0; i < 8; i++)
#pragma unroll
        for (int j = 0; j < 8; j++) acc[i][j] = 0.f;

    for (int k0 = 0; k0 < K; k0 += 8) {
        float4 av = aval ? *(const float4*)(Ap + k0) : make_float4(0.f,0.f,0.f,0.f);
        float4 bv = *(const float4*)(Bp + (size_t)k0 * N);
        As[acol + 0][arow] = av.x; As[acol + 1][arow] = av.y;
        As[acol + 2][arow] = av.z; As[acol + 3][arow] = av.w;
        *(float4*)&Bs[brow][bcol] = bv;
        __syncthreads();
#pragma unroll
        for (int kk = 0; kk < 8; kk++) {
            float a[8], b[8];
            *(float4*)&a[0] = *(const float4*)&As[kk][ty * 8];
            *(float4*)&a[4] = *(const float4*)&As[kk][ty * 8 + 4];
            *(float4*)&b[0] = *(const float4*)&Bs[kk][tx * 8];
            *(float4*)&b[4] = *(const float4*)&Bs[kk][tx * 8 + 4];
#pragma unroll
            for (int i = 0; i < 8; i++)
#pragma unroll
                for (int j = 0; j < 8; j++) acc[i][j] = fmaf(a[i], b[j], acc[i][j]);
        }
        __syncthreads();
    }

    int cbase = bx * 128 + tx * 8;
#pragma unroll
    for (int i = 0; i < 8; i++) {
        int r = by * 128 + ty * 8 + i;
        if (r >= M) continue;
        float* Cp = C + (size_t)r * N + cbase;
#pragma unroll
        for (int j = 0; j < 8; j++) {
            float v = acc[i][j] + bias[cbase + j];
            if (doRelu) v = fmaxf(v, 0.f);
            Cp[j] = v;
        }
    }
}

// ---------------- tf32 helpers ----------------
__device__ __forceinline__ uint32_t f2tf32(float v) {
    uint32_t r;
    asm("cvt.rna.tf32.f32 %0, %1;" : "=r"(r) : "f"(v));
    return r;
}
__device__ __forceinline__ void mma_tf32(
    float& c0, float& c1, float& c2, float& c3,
    uint32_t a0, uint32_t a1, uint32_t a2, uint32_t a3,
    uint32_t b0, uint32_t b1)
{
    asm volatile(
        "mma.sync.aligned.m16n8k8.row.col.f32.tf32.tf32.f32 "
        "{%0,%1,%2,%3}, {%4,%5,%6,%7}, {%8,%9}, {%0,%1,%2,%3};"
        : "+f"(c0), "+f"(c1), "+f"(c2), "+f"(c3)
        : "r"(a0), "r"(a1), "r"(a2), "r"(a3), "r"(b0), "r"(b1));
}

// ---------------- tf32 tensor GEMM (loss-only path) ----------------
#define SA 36
#define SB 37
template<int BMODE, int EPI>
__global__ __launch_bounds__(256) void tmma_kernel(
    const float* __restrict__ A, const float* __restrict__ B,
    const float* __restrict__ bias, float* __restrict__ C,
    int M, int N, int K, int doRelu, int rowmap)
{
    __shared__ uint32_t As[128 * SA];
    __shared__ uint32_t Bs[128 * SB];
    __shared__ float red[128];

    int tid = threadIdx.x;
    int bx = blockIdx.x, by = blockIdx.y;
    int wid = tid >> 5, lane = tid & 31;
    int wm = wid >> 1, wn = wid & 1;
    int g = lane >> 2, tg = lane & 3;

    if (EPI == 1 && tid < 128) red[tid] = 0.f;

    int arow = tid >> 1;
    int akh = (tid & 1) << 4;
    int agrow = by * 128 + arow;
    bool aval = agrow < M;
    long ar = agrow;
    if (rowmap && aval) ar = agrow + (agrow / 500) * 12;
    const float* Ap = A + (size_t)ar * K + akh;

    int bn_d = tid >> 1;
    int bkh_d = (tid & 1) << 4;
    int bgn_d = bx * 128 + bn_d;
    const float* Bp_d = B + (size_t)bgn_d * K + bkh_d;
    int bn_t = tid & 127;
    int bkh_t = (tid >> 7) << 4;
    const float* Bp_t = B + (size_t)(bx * 128 + bn_t);

    float acc[2][8][4];
#pragma unroll
    for (int mi = 0; mi < 2; mi++)
#pragma unroll
        for (int ni = 0; ni < 8; ni++)
#pragma unroll
            for (int q = 0; q < 4; q++) acc[mi][ni][q] = 0.f;

    for (int k0 = 0; k0 < K; k0 += 32) {
#pragma unroll
        for (int i = 0; i < 4; i++) {
            float4 v = aval ? *(const float4*)(Ap + k0 + i * 4)
                            : make_float4(0.f,0.f,0.f,0.f);
            uint32_t* d = &As[arow * SA + akh + i * 4];
            d[0] = f2tf32(v.x); d[1] = f2tf32(v.y);
            d[2] = f2tf32(v.z); d[3] = f2tf32(v.w);
        }
        if (BMODE == 1) {
            bool bv = bgn_d < N;
#pragma unroll
            for (int i = 0; i < 4; i++) {
                float4 v = bv ? *(const float4*)(Bp_d + k0 + i * 4)
                              : make_float4(0.f,0.f,0.f,0.f);
                uint32_t* d = &Bs[bn_d * SB + bkh_d + i * 4];
                d[0] = f2tf32(v.x); d[1] = f2tf32(v.y);
                d[2] = f2tf32(v.z); d[3] = f2tf32(v.w);
            }
        } else {
#pragma unroll
            for (int j = 0; j < 16; j++) {
                int k = bkh_t + j;
                float v = Bp_t[(size_t)(k0 + k) * N];
                Bs[bn_t * SB + k] = f2tf32(v);
            }
        }
        __syncthreads();

#pragma unroll
        for (int ks = 0; ks < 4; ks++) {
            int kb = ks * 8;
            uint32_t a[2][4];
#pragma unroll
            for (int mi = 0; mi < 2; mi++) {
                int r = wm * 32 + mi * 16;
                a[mi][0] = As[(r + g    ) * SA + kb + tg];
                a[mi][1] = As[(r + g + 8) * SA + kb + tg];
                a[mi][2] = As[(r + g    ) * SA + kb + tg + 4];
                a[mi][3] = As[(r + g + 8) * SA + kb + tg + 4];
            }
#pragma unroll
            for (int ni = 0; ni < 8; ni++) {
                int n = wn * 64 + ni * 8;
                uint32_t b0 = Bs[(n + g) * SB + kb + tg];
                uint32_t b1 = Bs[(n + g) * SB + kb + tg + 4];
#pragma unroll
                for (int mi = 0; mi < 2; mi++)
                    mma_tf32(acc[mi][ni][0], acc[mi][ni][1],
                             acc[mi][ni][2], acc[mi][ni][3],
                             a[mi][0], a[mi][1], a[mi][2], a[mi][3], b0, b1);
            }
        }
        __syncthreads();
    }

    if (EPI == 0) {
#pragma unroll
        for (int mi = 0; mi < 2; mi++) {
            int r0 = by * 128 + wm * 32 + mi * 16 + g;
#pragma unroll
            for (int ni = 0; ni < 8; ni++) {
                int cg = bx * 128 + wn * 64 + ni * 8 + tg * 2;
                float b0v = bias[cg], b1v = bias[cg + 1];
                float v0 = acc[mi][ni][0] + b0v;
                float v1 = acc[mi][ni][1] + b1v;
                float v2 = acc[mi][ni][2] + b0v;
                float v3 = acc[mi][ni][3] + b1v;
                if (doRelu) {
                    v0 = fmaxf(v0, 0.f); v1 = fmaxf(v1, 0.f);
                    v2 = fmaxf(v2, 0.f); v3 = fmaxf(v3, 0.f);
                }
                if (r0 < M)     *(float2*)&C[(size_t)r0 * N + cg]       = make_float2(v0, v1);
                if (r0 + 8 < M) *(float2*)&C[(size_t)(r0 + 8) * N + cg] = make_float2(v2, v3);
            }
        }
    } else {
        float rsum[2][2] = {{0.f,0.f},{0.f,0.f}};
#pragma unroll
        for (int ni = 0; ni < 8; ni++) {
            int cg0 = bx * 128 + wn * 64 + ni * 8 + tg * 2;
#pragma unroll
            for (int half = 0; half < 2; half++) {
                int cg = cg0 + half;
                if (cg >= NCOLS) continue;
                int cb = cg / 511;
                int mm = cg - cb * 511;
#pragma unroll
                for (int mi = 0; mi < 2; mi++) {
#pragma unroll
                    for (int rh = 0; rh < 2; rh++) {
                        int rg = by * 128 + wm * 32 + mi * 16 + rh * 8 + g;
                        if (rg >= NROWS) continue;
                        float s = acc[mi][ni][rh * 2 + half];
                        float e = __expf(s - 10.0f);
                        rsum[mi][rh] += e;
                        if (mm < 11) atomicAdd(&g_low[rg * 11 + mm], e);
                        else if (mm >= 500) atomicAdd(&g_high[rg * 11 + mm - 500], e);
                        int bi = rg / 500;
                        if (cb == bi) {
                            int dd = mm - (rg - bi * 500);
                            if (dd >= 0 && dd < 12) g_diag[rg * 12 + dd] = s;
                        }
                    }
                }
            }
        }
#pragma unroll
        for (int mi = 0; mi < 2; mi++)
#pragma unroll
            for (int rh = 0; rh < 2; rh++) {
                float v = rsum[mi][rh];
                v += __shfl_xor_sync(0xffffffffu, v, 1);
                v += __shfl_xor_sync(0xffffffffu, v, 2);
                if (tg == 0)
                    atomicAdd(&red[wm * 32 + mi * 16 + rh * 8 + g], v);
            }
        __syncthreads();
        if (tid < 128) {
            int rr = by * 128 + tid;
            if (rr < NROWS && red[tid] != 0.f) atomicAdd(&g_E[rr], red[tid]);
        }
    }
}

// ---------------- GRU persistent kernel v2 ----------------
// 128 CTAs x 256 threads, all co-resident. CTA owns 4 cols x 3 gates.
// w_s laid out [k][12] so each k-iter is 3x LDS.128 + 12 FMA.
// k-split: thread group ks owns k in [ks*32, ks*32+32).
// No gpu-scope fences: h via st.cg/ld.cg (L2-coherent), barrier via
// red.release.gpu + ld.acquire.gpu, chained through bar.sync.
__global__ __launch_bounds__(256) void gru_kernel(
    const float* __restrict__ wh, const float* __restrict__ bhn,
    float* __restrict__ cOut)
{
    __shared__ float w_s[512 * 12];     // [k][gate*4 + cc]
    __shared__ float red[192 * 17];
    __shared__ float dot_s[192];
    __shared__ float bhn_s[4];
    int tid = threadIdx.x;
    int colBase = blockIdx.x * 4;

    for (int e = tid; e < 6144; e += 256) {
        int k = e / 12, r = e - k * 12;
        int g = r >> 2, cc = r & 3;
        w_s[e] = wh[(size_t)k * 1536 + g * 512 + colBase + cc];
    }
    if (tid < 4) bhn_s[tid] = bhn[colBase + tid];

    unsigned* barp; { unsigned* t_; asm("mov.u64 %0, g_bar;" : "=l"(t_)); barp = t_; }
    __syncthreads();

    int ks = tid >> 4;          // 0..15, owns k in [ks*32, ks*32+32)
    int row = tid & 15;         // batch
    int kbase = ks * 32;
    int grow2 = tid >> 2;       // gate thread: batch row (tid<64)
    int gcol = colBase + (tid & 3);

    for (int t = 0; t < 512; t++) {
        int rb = t & 1;
        const float* hb = g_hbuf[rb];

        float xr = 0.f, xu = 0.f, xn = 0.f, hold = 0.f;
        if (tid < 64) {
            size_t base = ((size_t)(grow2 << 9) + t) * 1536 + gcol;
            xr = __ldg(&g_xi[base]);
            xu = __ldg(&g_xi[base + 512]);
            xn = __ldg(&g_xi[base + 1024]);
            hold = __ldcg(&hb[gcol * 16 + grow2]);
        }

        float acc[12];
#pragma unroll
        for (int g = 0; g < 12; g++) acc[g] = 0.f;
#pragma unroll 8
        for (int j = 0; j < 32; j++) {
            int k = kbase + j;
            float hv = __ldcg(&hb[k * 16 + row]);
            const float4* w4 = (const float4*)&w_s[k * 12];
            float4 wr = w4[0], wu = w4[1], wn4 = w4[2];
            acc[0]  = fmaf(wr.x,  hv, acc[0]);
            acc[1]  = fmaf(wr.y,  hv, acc[1]);
            acc[2]  = fmaf(wr.z,  hv, acc[2]);
            acc[3]  = fmaf(wr.w,  hv, acc[3]);
            acc[4]  = fmaf(wu.x,  hv, acc[4]);
            acc[5]  = fmaf(wu.y,  hv, acc[5]);
            acc[6]  = fmaf(wu.z,  hv, acc[6]);
            acc[7]  = fmaf(wu.w,  hv, acc[7]);
            acc[8]  = fmaf(wn4.x, hv, acc[8]);
            acc[9]  = fmaf(wn4.y, hv, acc[9]);
            acc[10] = fmaf(wn4.z, hv, acc[10]);
            acc[11] = fmaf(wn4.w, hv, acc[11]);
        }
#pragma unroll
        for (int g = 0; g < 12; g++) red[(row * 12 + g) * 17 + ks] = acc[g];
        __syncthreads();

        if (tid < 192) {
            float v = 0.f;
#pragma unroll
            for (int s = 0; s < 16; s++) v += red[tid * 17 + s];
            dot_s[tid] = v;
        }
        __syncthreads();

        if (tid < 64) {
            int cc = tid & 3;
            float hr = dot_s[grow2 * 12 + cc];
            float hu = dot_s[grow2 * 12 + 4 + cc];
            float hn = dot_s[grow2 * 12 + 8 + cc];
            float r = 1.f / (1.f + __expf(-(xr + hr)));
            float u = 1.f / (1.f + __expf(-(xu + hu)));
            float n = tanhf(xn + r * (hn + bhn_s[cc]));
            float hnew = (1.f - u) * n + u * hold;
            stcg(&g_hbuf[rb ^ 1][gcol * 16 + grow2], hnew);
            cOut[((size_t)(grow2 << 9) + t) * 512 + gcol] = hnew;
        }

        __syncthreads();               // orders gate threads' st.cg before tid0's release
        if (tid == 0) {
            red_release_gpu(barp, 1u);
            unsigned tgt = 128u * (unsigned)(t + 1);
            while (ld_acquire_gpu(barp) < tgt) { }
        }
        __syncthreads();               // propagates tid0's acquire to all threads
    }
}

// ---------------- row L2-normalize ----------------
__device__ __forceinline__ void norm_row(const float* src, float* dst, int lane, float extraScale) {
    float4 a = ((const float4*)src)[lane];
    float4 b = ((const float4*)src)[lane + 32];
    float ss = a.x*a.x + a.y*a.y + a.z*a.z + a.w*a.w
             + b.x*b.x + b.y*b.y + b.z*b.z + b.w*b.w;
#pragma unroll
    for (int o = 16; o > 0; o >>= 1) ss += __shfl_xor_sync(0xffffffffu, ss, o);
    float r = rsqrtf(ss);
    r = r * (1.5f - 0.5f * ss * r * r);
    r *= extraScale;
    a.x*=r; a.y*=r; a.z*=r; a.w*=r; b.x*=r; b.y*=r; b.z*=r; b.w*=r;
    ((float4*)dst)[lane] = a;
    ((float4*)dst)[lane + 32] = b;
}

__global__ void norm_p_kernel() {
    int w = (blockIdx.x * blockDim.x + threadIdx.x) >> 5;
    if (w >= NROWS) return;
    norm_row(g_p + (size_t)w * 256, g_p + (size_t)w * 256, threadIdx.x & 31, 10.0f);
}

__global__ void build_zn_kernel(const float* __restrict__ z) {
    int w = (blockIdx.x * blockDim.x + threadIdx.x) >> 5;
    if (w >= NCOLS) return;
    int b = w / 511, tt = w % 511;
    const float* src = z + (size_t)(b * 512 + tt + 1) * 256;
    norm_row(src, g_zn + (size_t)w * 256, threadIdx.x & 31, 1.0f);
}

// ---------------- loss finisher ----------------
__global__ void loss_kernel(float* __restrict__ out) {
    __shared__ float part[1024];
    int tid = threadIdx.x;
    float tot = 0.f;
    for (int i = tid; i < NROWS; i += 1024) {
        float E = g_E[i];
        float L[11], H[11];
        float low = 0.f, high = 0.f;
#pragma unroll
        for (int j = 0; j < 11; j++) {
            L[j] = g_low[i * 11 + j];
            H[j] = g_high[i * 11 + j];
            high += H[j];
        }
#pragma unroll
        for (int k = 1; k <= 12; k++) {
            if (k >= 2) { low += L[k - 2]; high -= H[k - 2]; }
            float window = E - low - high;
            tot += g_diag[i * 12 + (k - 1)] - (10.0f + logf(window));
        }
    }
    part[tid] = tot;
    __syncthreads();
    for (int s = 512; s > 0; s >>= 1) {
        if (tid < s) part[tid] += part[tid + s];
        __syncthreads();
    }
    if (tid == 0) out[0] = -part[0] / (12.0f * (float)NROWS);
}

// ---------------- driver ----------------
extern "C" void kernel_launch(void* const* d_in, const int* in_sizes, int n_in,
                              void* d_out, int out_size) {
    const float* x       = (const float*)d_in[0];
    const float* enc_w1  = (const float*)d_in[1];
    const float* enc_b1  = (const float*)d_in[2];
    const float* enc_w2  = (const float*)d_in[3];
    const float* enc_b2  = (const float*)d_in[4];
    const float* enc_w3  = (const float*)d_in[5];
    const float* enc_b3  = (const float*)d_in[6];
    const float* gru_wi  = (const float*)d_in[7];
    const float* gru_bi  = (const float*)d_in[8];
    const float* gru_wh  = (const float*)d_in[9];
    const float* gru_bhn = (const float*)d_in[10];
    const float* pred_w1 = (const float*)d_in[11];
    const float* pred_b1 = (const float*)d_in[12];
    const float* pred_w2 = (const float*)d_in[13];
    const float* pred_b2 = (const float*)d_in[14];

    float* out  = (float*)d_out;
    float* zOut = out;                       // [8192, 256]
    float* cOut = out + 2097152;             // [8192, 512]
    float* lOut = out + (out_size - 1);

    // Resolve true device addresses of scratch symbols (host-shadow trap!)
    float *h1, *h2, *xi, *ph, *p, *zn;
    cudaGetSymbolAddress((void**)&h1, g_h1);
    cudaGetSymbolAddress((void**)&h2, g_h2);
    cudaGetSymbolAddress((void**)&xi, g_xi);
    cudaGetSymbolAddress((void**)&ph, g_ph);
    cudaGetSymbolAddress((void**)&p,  g_p);
    cudaGetSymbolAddress((void**)&zn, g_zn);

    reset_kernel<<<64, 256>>>();

    dim3 t256(256);
    // encoder (fp32 — z exactness)
    sgemm128<<<dim3(4, 64),  t256>>>(x,    enc_w1, enc_b1, h1,   8192, 512,  128, 1, 0);
    sgemm128<<<dim3(4, 64),  t256>>>(h1,   enc_w2, enc_b2, h2,   8192, 512,  512, 1, 0);
    sgemm128<<<dim3(2, 64),  t256>>>(h2,   enc_w3, enc_b3, zOut, 8192, 256,  512, 0, 0);
    // GRU input projection (fp32 — c accuracy)
    sgemm128<<<dim3(12, 64), t256>>>(zOut, gru_wi, gru_bi, xi,   8192, 1536, 256, 0, 0);
    // GRU recurrence (v2: no gpu fences, vectorized weight loads)
    gru_kernel<<<128, 256>>>(gru_wh, gru_bhn, cOut);
    // prediction net on c[:, :-12] — tf32 tensor cores (loss-only path)
    tmma_kernel<0,0><<<dim3(4, 63), t256>>>(cOut, pred_w1, pred_b1, ph, 8000, 512, 512, 1, 1);
    tmma_kernel<0,0><<<dim3(2, 63), t256>>>(ph,   pred_w2, pred_b2, p,  8000, 256, 512, 0, 0);
    // normalize
    norm_p_kernel<<<1000, 256>>>();
    build_zn_kernel<<<1022, 256>>>(zOut);
    // fused Gram + epilogue — tf32 tensor cores
    tmma_kernel<1,1><<<dim3(64, 63), t256>>>(p, zn, nullptr, nullptr, NROWS, NCOLS, 256, 0, 0);
    // loss
    loss_kernel<<<1, 1024>>>(lOut);
}